// round 1
// baseline (speedup 1.0000x reference)
#include <cuda_runtime.h>

#define NN   1024
#define FF   200
#define MTOT 65536
#define NEG  0.2f

// ---------------- scratch (device globals: no allocation allowed) ----------
__device__ float g_h0[NN * FF];          // h rows 0..1023
__device__ float g_as[NN];
__device__ float g_ad[NN];
__device__ float g_m[NN];                // row max of scores
__device__ float g_den[NN];              // softmax denominator
__device__ float g_part[4][NN * FF];     // K-split partials of alpha@h0

__device__ __forceinline__ float leaky(float z) { return z > 0.f ? z : NEG * z; }

// ---------------- Kernel A: h = x @ W (+bias for rows >= NN) ---------------
#define BM 64
#define BK 8
__global__ void __launch_bounds__(200) gemm_main(const float* __restrict__ x,
                                                 const float* __restrict__ W,
                                                 const float* __restrict__ bias,
                                                 float* __restrict__ out) {
    __shared__ __align__(16) float As[BM * BK];   // [m][k]
    __shared__ __align__(16) float Bs[BK * FF];   // [k][n]
    const int tid = threadIdx.x;                  // 0..199
    const int tx  = tid % 25;                     // col group: cols tx*8..+8
    const int ty  = tid / 25;                     // row group: rows ty*8..+8
    const int row0 = blockIdx.x * BM;

    float acc[8][8];
#pragma unroll
    for (int v = 0; v < 8; v++)
#pragma unroll
        for (int u = 0; u < 8; u++) acc[v][u] = 0.f;

    for (int k0 = 0; k0 < FF; k0 += BK) {
        // A tile 64x8 via float2 (256 float2 elements over 200 threads)
        for (int idx = tid; idx < BM * BK / 2; idx += 200) {
            int m = idx >> 2, k2 = idx & 3;
            float2 v = *reinterpret_cast<const float2*>(x + (row0 + m) * FF + k0 + 2 * k2);
            *reinterpret_cast<float2*>(&As[m * BK + 2 * k2]) = v;
        }
        // B tile 8x200 via float4 (400 float4 over 200 threads: exactly 2 each)
        for (int idx = tid; idx < BK * FF / 4; idx += 200) {
            int k = idx / 50, n4 = idx % 50;
            float4 v = *reinterpret_cast<const float4*>(W + (k0 + k) * FF + n4 * 4);
            *reinterpret_cast<float4*>(&Bs[k * FF + n4 * 4]) = v;
        }
        __syncthreads();
#pragma unroll
        for (int k = 0; k < BK; k++) {
            float a[8], b[8];
#pragma unroll
            for (int v = 0; v < 8; v++) a[v] = As[(ty * 8 + v) * BK + k];
            float4 b0 = *reinterpret_cast<const float4*>(&Bs[k * FF + tx * 8]);
            float4 b1 = *reinterpret_cast<const float4*>(&Bs[k * FF + tx * 8 + 4]);
            b[0] = b0.x; b[1] = b0.y; b[2] = b0.z; b[3] = b0.w;
            b[4] = b1.x; b[5] = b1.y; b[6] = b1.z; b[7] = b1.w;
#pragma unroll
            for (int v = 0; v < 8; v++)
#pragma unroll
                for (int u = 0; u < 8; u++) acc[v][u] = fmaf(a[v], b[u], acc[v][u]);
        }
        __syncthreads();
    }

    const int col = tx * 8;
    if (row0 < NN) {  // blocks are 64-row aligned; NN % 64 == 0, so whole block is in h0 region
#pragma unroll
        for (int v = 0; v < 8; v++) {
            int r = row0 + ty * 8 + v;
            float4 o0 = make_float4(acc[v][0], acc[v][1], acc[v][2], acc[v][3]);
            float4 o1 = make_float4(acc[v][4], acc[v][5], acc[v][6], acc[v][7]);
            *reinterpret_cast<float4*>(&g_h0[r * FF + col])     = o0;
            *reinterpret_cast<float4*>(&g_h0[r * FF + col + 4]) = o1;
        }
    } else {
        float4 bb0 = *reinterpret_cast<const float4*>(bias + col);
        float4 bb1 = *reinterpret_cast<const float4*>(bias + col + 4);
#pragma unroll
        for (int v = 0; v < 8; v++) {
            int r = row0 + ty * 8 + v;
            float4 o0 = make_float4(acc[v][0] + bb0.x, acc[v][1] + bb0.y,
                                    acc[v][2] + bb0.z, acc[v][3] + bb0.w);
            float4 o1 = make_float4(acc[v][4] + bb1.x, acc[v][5] + bb1.y,
                                    acc[v][6] + bb1.z, acc[v][7] + bb1.w);
            *reinterpret_cast<float4*>(out + r * FF + col)     = o0;
            *reinterpret_cast<float4*>(out + r * FF + col + 4) = o1;
        }
    }
}

// ---------------- Kernel B: a_s = h0@att_src, a_d = h0@att_dst -------------
__global__ void __launch_bounds__(256) attvec(const float* __restrict__ att_src,
                                              const float* __restrict__ att_dst) {
    int gw   = (blockIdx.x * blockDim.x + threadIdx.x) >> 5;
    int lane = threadIdx.x & 31;
    if (gw >= NN) return;
    float s = 0.f, d = 0.f;
    for (int c = lane; c < FF; c += 32) {
        float h = g_h0[gw * FF + c];
        s = fmaf(h, att_src[c], s);
        d = fmaf(h, att_dst[c], d);
    }
#pragma unroll
    for (int o = 16; o; o >>= 1) {
        s += __shfl_xor_sync(0xffffffffu, s, o);
        d += __shfl_xor_sync(0xffffffffu, d, o);
    }
    if (lane == 0) { g_as[gw] = s; g_ad[gw] = d; }
}

// ---------------- Kernel C: per-row max + softmax denominator --------------
// leaky_relu is monotone increasing -> max_j leaky(ad_i + as_j) = leaky(ad_i + max(as))
__global__ void __launch_bounds__(256) softprep() {
    __shared__ float s_as[NN];
    __shared__ float red[8];
    int tid = threadIdx.x, lane = tid & 31, wid = tid >> 5;
    float lm = -1e30f;
    for (int j = tid; j < NN; j += 256) {
        float v = g_as[j];
        s_as[j] = v;
        lm = fmaxf(lm, v);
    }
#pragma unroll
    for (int o = 16; o; o >>= 1) lm = fmaxf(lm, __shfl_xor_sync(0xffffffffu, lm, o));
    if (lane == 0) red[wid] = lm;
    __syncthreads();
    float maxs = red[0];
#pragma unroll
    for (int w = 1; w < 8; w++) maxs = fmaxf(maxs, red[w]);

    int row = blockIdx.x * 8 + wid;   // 8 rows per block (one per warp)
    float ad = g_ad[row];
    float mi = leaky(ad + maxs);
    float sum = 0.f;
    for (int j = lane; j < NN; j += 32)
        sum += __expf(leaky(ad + s_as[j]) - mi);
#pragma unroll
    for (int o = 16; o; o >>= 1) sum += __shfl_xor_sync(0xffffffffu, sum, o);
    if (lane == 0) { g_m[row] = mi; g_den[row] = sum; }
}

// ---------------- Kernel D: partial[ks] = E_chunk @ h0_chunk ---------------
#define DM 32
__global__ void __launch_bounds__(200) attn_gemm() {
    __shared__ __align__(16) float sh_h[DM * FF];   // 25.6 KB
    __shared__ __align__(16) float sh_e[DM * DM];   // [j][i], 4 KB
    const int tid = threadIdx.x;        // 200
    const int cg = tid % 25;            // cols cg*8..+8
    const int ig = tid / 25;            // rows ig*4..+4
    const int row0 = blockIdx.x * DM;
    const int ks = blockIdx.y;          // K-split: j in [ks*256, ks*256+256)

    float acc[4][8];
#pragma unroll
    for (int v = 0; v < 4; v++)
#pragma unroll
        for (int u = 0; u < 8; u++) acc[v][u] = 0.f;

    for (int j0 = ks * 256; j0 < ks * 256 + 256; j0 += DM) {
        // h0 chunk 32x200 via float4 (1600 float4 over 200 threads: exactly 8 each)
#pragma unroll
        for (int t = 0; t < 8; t++) {
            int idx = tid + t * 200;
            int j = idx / 50, n4 = idx % 50;
            *reinterpret_cast<float4*>(&sh_h[j * FF + n4 * 4]) =
                *reinterpret_cast<const float4*>(&g_h0[(j0 + j) * FF + n4 * 4]);
        }
        // e tile 32x32
        for (int idx = tid; idx < DM * DM; idx += 200) {
            int j = idx >> 5, i = idx & 31;
            float z = leaky(g_ad[row0 + i] + g_as[j0 + j]);
            sh_e[j * DM + i] = __expf(z - g_m[row0 + i]);
        }
        __syncthreads();
#pragma unroll 4
        for (int j = 0; j < DM; j++) {
            float4 ev  = *reinterpret_cast<const float4*>(&sh_e[j * DM + ig * 4]);
            float4 h0v = *reinterpret_cast<const float4*>(&sh_h[j * FF + cg * 8]);
            float4 h1v = *reinterpret_cast<const float4*>(&sh_h[j * FF + cg * 8 + 4]);
            float e[4] = {ev.x, ev.y, ev.z, ev.w};
            float h[8] = {h0v.x, h0v.y, h0v.z, h0v.w, h1v.x, h1v.y, h1v.z, h1v.w};
#pragma unroll
            for (int v = 0; v < 4; v++)
#pragma unroll
                for (int u = 0; u < 8; u++) acc[v][u] = fmaf(e[v], h[u], acc[v][u]);
        }
        __syncthreads();
    }
    const int col = cg * 8;
#pragma unroll
    for (int v = 0; v < 4; v++) {
        int r = row0 + ig * 4 + v;
        float4 o0 = make_float4(acc[v][0], acc[v][1], acc[v][2], acc[v][3]);
        float4 o1 = make_float4(acc[v][4], acc[v][5], acc[v][6], acc[v][7]);
        *reinterpret_cast<float4*>(&g_part[ks][r * FF + col])     = o0;
        *reinterpret_cast<float4*>(&g_part[ks][r * FF + col + 4]) = o1;
    }
}

// ---------------- Kernel E: out0 = (sum partials)/den + bias ---------------
__global__ void __launch_bounds__(256) finalize(const float* __restrict__ bias,
                                                float* __restrict__ out) {
    int idx = blockIdx.x * 256 + threadIdx.x;
    if (idx >= NN * FF) return;
    int i = idx / FF, c = idx % FF;
    float s = g_part[0][idx] + g_part[1][idx] + g_part[2][idx] + g_part[3][idx];
    out[idx] = s / g_den[i] + bias[c];
}

// ---------------------------------------------------------------------------
extern "C" void kernel_launch(void* const* d_in, const int* in_sizes, int n_in,
                              void* d_out, int out_size) {
    const float* x       = (const float*)d_in[0];
    const float* W       = (const float*)d_in[1];
    const float* att_src = (const float*)d_in[2];
    const float* att_dst = (const float*)d_in[3];
    const float* bias    = (const float*)d_in[4];
    float* out = (float*)d_out;

    gemm_main<<<MTOT / BM, 200>>>(x, W, bias, out);
    attvec<<<NN * 32 / 256, 256>>>(att_src, att_dst);
    softprep<<<NN / 8, 256>>>();
    attn_gemm<<<dim3(NN / DM, 4), 200>>>();
    finalize<<<(NN * FF + 255) / 256, 256>>>(bias, out);
}

// round 3
// speedup vs baseline: 2.3819x; 2.3819x over previous
#include <cuda_runtime.h>
#include <cuda_bf16.h>
#include <cstdint>

#define NN   1024
#define FF   200
#define MTOT 65536
#define NEG  0.2f

#define BM 64
#define BK 16
#define KSTEPS 13          // ceil(200/16) -> padded K = 208
#define BNP 208            // padded N (200 -> 208)
#define ASTR 24            // smem row stride in bf16 (48B, conflict-free ldmatrix)
#define KS_ATT 8           // attention K-splits

// ---------------- scratch (device globals: no allocation allowed) ----------
__device__ float g_h0[NN * FF];
__device__ float g_as[NN];
__device__ float g_ad[NN];
__device__ float g_m[NN];
__device__ float g_den[NN];
__device__ float g_part[KS_ATT][NN * FF];
// W pre-split into bf16 hi/lo, transposed to [n][k], blocked by k-step:
// layout: offset = (ks*BNP + n)*BK + kk
__device__ __align__(16) __nv_bfloat16 g_Wb_h[KSTEPS * BNP * BK];
__device__ __align__(16) __nv_bfloat16 g_Wb_l[KSTEPS * BNP * BK];

__device__ __forceinline__ float leaky(float z) { return z > 0.f ? z : NEG * z; }

// ---------------- Kernel P: split W into bf16 hi/lo, blocked transpose -----
__global__ void __launch_bounds__(256) prep_W(const float* __restrict__ W) {
    int id = blockIdx.x * 256 + threadIdx.x;
    if (id >= KSTEPS * BNP * BK) return;
    int kk = id % BK;
    int n  = (id / BK) % BNP;
    int ks = id / (BK * BNP);
    int k  = ks * BK + kk;
    float v = (k < FF && n < FF) ? W[k * FF + n] : 0.f;
    __nv_bfloat16 hi = __float2bfloat16_rn(v);
    float rem = v - __bfloat162float(hi);
    g_Wb_h[id] = hi;
    g_Wb_l[id] = __float2bfloat16_rn(rem);
}

// ---------------- Kernel A: h = x @ W via bf16 MMA (3-pass hi/lo split) ----
__global__ void __launch_bounds__(256) gemm_mma(const float* __restrict__ x,
                                                const float* __restrict__ bias,
                                                float* __restrict__ out) {
    __shared__ __align__(16) __nv_bfloat16 As_h[BM * ASTR];
    __shared__ __align__(16) __nv_bfloat16 As_l[BM * ASTR];
    __shared__ __align__(16) __nv_bfloat16 Bs_h[BNP * ASTR];
    __shared__ __align__(16) __nv_bfloat16 Bs_l[BNP * ASTR];

    const int tid  = threadIdx.x;
    const int lane = tid & 31;
    const int warp = tid >> 5;
    const int warp_m = warp >> 1;         // 0..3 -> rows warp_m*16
    const int warp_n = warp & 1;          // 0..1 -> cols warp_n*104
    const int m_base = warp_m * 16;
    const int n_base = warp_n * 104;      // 13 n-tiles of 8
    const int row0 = blockIdx.x * BM;

    // ldmatrix source addresses (per-lane)
    const int mi   = lane >> 3;           // matrix selector 0..3
    const int lrow = lane & 7;
    const uint32_t a_h_base = (uint32_t)__cvta_generic_to_shared(As_h);
    const uint32_t a_l_base = (uint32_t)__cvta_generic_to_shared(As_l);
    const uint32_t b_h_base = (uint32_t)__cvta_generic_to_shared(Bs_h);
    const uint32_t b_l_base = (uint32_t)__cvta_generic_to_shared(Bs_l);
    const uint32_t a_off = ((m_base + lrow + (mi & 1) * 8) * ASTR + (mi >> 1) * 8) * 2;
    const uint32_t b_off0 = ((n_base + lrow) * ASTR + ((lane >> 3) & 1) * 8) * 2;

    float acc[13][4];
#pragma unroll
    for (int t = 0; t < 13; t++)
#pragma unroll
        for (int u = 0; u < 4; u++) acc[t][u] = 0.f;

    // A gmem mapping: 256 threads cover 64 rows x 4 float4
    const int am = tid >> 2;
    const int af = tid & 3;

    for (int ks = 0; ks < KSTEPS; ks++) {
        // ---- load A tile (64 x 16 f32) -> split to bf16 hi/lo in smem ----
        {
            int col = ks * BK + af * 4;
            float4 v = (col < FF)
                ? *reinterpret_cast<const float4*>(x + (row0 + am) * FF + col)
                : make_float4(0.f, 0.f, 0.f, 0.f);
            __nv_bfloat16 h0 = __float2bfloat16_rn(v.x);
            __nv_bfloat16 h1 = __float2bfloat16_rn(v.y);
            __nv_bfloat16 h2 = __float2bfloat16_rn(v.z);
            __nv_bfloat16 h3 = __float2bfloat16_rn(v.w);
            __nv_bfloat16 l0 = __float2bfloat16_rn(v.x - __bfloat162float(h0));
            __nv_bfloat16 l1 = __float2bfloat16_rn(v.y - __bfloat162float(h1));
            __nv_bfloat16 l2 = __float2bfloat16_rn(v.z - __bfloat162float(h2));
            __nv_bfloat16 l3 = __float2bfloat16_rn(v.w - __bfloat162float(h3));
            int base = am * ASTR + af * 4;
            uint32_t ph0 = ((uint32_t)__bfloat16_as_ushort(h1) << 16) | __bfloat16_as_ushort(h0);
            uint32_t ph1 = ((uint32_t)__bfloat16_as_ushort(h3) << 16) | __bfloat16_as_ushort(h2);
            uint32_t pl0 = ((uint32_t)__bfloat16_as_ushort(l1) << 16) | __bfloat16_as_ushort(l0);
            uint32_t pl1 = ((uint32_t)__bfloat16_as_ushort(l3) << 16) | __bfloat16_as_ushort(l2);
            *reinterpret_cast<uint32_t*>(&As_h[base])     = ph0;
            *reinterpret_cast<uint32_t*>(&As_h[base + 2]) = ph1;
            *reinterpret_cast<uint32_t*>(&As_l[base])     = pl0;
            *reinterpret_cast<uint32_t*>(&As_l[base + 2]) = pl1;
        }
        // ---- load B tile (208 n-rows x 16 k) as int4 copies ----
        {
            const int4* srcH = reinterpret_cast<const int4*>(g_Wb_h) + ks * (BNP * 2);
            const int4* srcL = reinterpret_cast<const int4*>(g_Wb_l) + ks * (BNP * 2);
#pragma unroll
            for (int idx = tid; idx < BNP * 2; idx += 256) {
                int n = idx >> 1, half = idx & 1;
                *reinterpret_cast<int4*>(&Bs_h[n * ASTR + half * 8]) = srcH[idx];
                *reinterpret_cast<int4*>(&Bs_l[n * ASTR + half * 8]) = srcL[idx];
            }
        }
        __syncthreads();

        // ---- A fragments ----
        uint32_t ah0, ah1, ah2, ah3, al0, al1, al2, al3;
        asm volatile("ldmatrix.sync.aligned.m8n8.x4.shared.b16 {%0,%1,%2,%3}, [%4];"
                     : "=r"(ah0), "=r"(ah1), "=r"(ah2), "=r"(ah3) : "r"(a_h_base + a_off));
        asm volatile("ldmatrix.sync.aligned.m8n8.x4.shared.b16 {%0,%1,%2,%3}, [%4];"
                     : "=r"(al0), "=r"(al1), "=r"(al2), "=r"(al3) : "r"(a_l_base + a_off));

        // ---- 13 n-tiles ----
#pragma unroll
        for (int nt = 0; nt < 13; nt++) {
            uint32_t boff = b_off0 + nt * (8 * ASTR * 2);
            uint32_t bh0, bh1, bl0, bl1;
            asm volatile("ldmatrix.sync.aligned.m8n8.x2.shared.b16 {%0,%1}, [%2];"
                         : "=r"(bh0), "=r"(bh1) : "r"(b_h_base + boff));
            asm volatile("ldmatrix.sync.aligned.m8n8.x2.shared.b16 {%0,%1}, [%2];"
                         : "=r"(bl0), "=r"(bl1) : "r"(b_l_base + boff));
            asm volatile("mma.sync.aligned.m16n8k16.row.col.f32.bf16.bf16.f32 "
                         "{%0,%1,%2,%3}, {%4,%5,%6,%7}, {%8,%9}, {%0,%1,%2,%3};"
                         : "+f"(acc[nt][0]), "+f"(acc[nt][1]), "+f"(acc[nt][2]), "+f"(acc[nt][3])
                         : "r"(ah0), "r"(ah1), "r"(ah2), "r"(ah3), "r"(bh0), "r"(bh1));
            asm volatile("mma.sync.aligned.m16n8k16.row.col.f32.bf16.bf16.f32 "
                         "{%0,%1,%2,%3}, {%4,%5,%6,%7}, {%8,%9}, {%0,%1,%2,%3};"
                         : "+f"(acc[nt][0]), "+f"(acc[nt][1]), "+f"(acc[nt][2]), "+f"(acc[nt][3])
                         : "r"(ah0), "r"(ah1), "r"(ah2), "r"(ah3), "r"(bl0), "r"(bl1));
            asm volatile("mma.sync.aligned.m16n8k16.row.col.f32.bf16.bf16.f32 "
                         "{%0,%1,%2,%3}, {%4,%5,%6,%7}, {%8,%9}, {%0,%1,%2,%3};"
                         : "+f"(acc[nt][0]), "+f"(acc[nt][1]), "+f"(acc[nt][2]), "+f"(acc[nt][3])
                         : "r"(al0), "r"(al1), "r"(al2), "r"(al3), "r"(bh0), "r"(bh1));
        }
        __syncthreads();
    }

    // ---- epilogue ----
    const int g   = lane >> 2;
    const int tig = lane & 3;
    const int r0 = row0 + m_base + g;
    const int r1 = r0 + 8;
    const bool to_h0 = (row0 < NN);     // whole 64-row block on one side (1024 % 64 == 0)
#pragma unroll
    for (int nt = 0; nt < 13; nt++) {
        int col = n_base + nt * 8 + tig * 2;
        if (col >= FF) continue;
        if (to_h0) {
            *reinterpret_cast<float2*>(&g_h0[r0 * FF + col]) = make_float2(acc[nt][0], acc[nt][1]);
            *reinterpret_cast<float2*>(&g_h0[r1 * FF + col]) = make_float2(acc[nt][2], acc[nt][3]);
        } else {
            float b0 = bias[col], b1 = bias[col + 1];
            *reinterpret_cast<float2*>(&out[r0 * FF + col]) = make_float2(acc[nt][0] + b0, acc[nt][1] + b1);
            *reinterpret_cast<float2*>(&out[r1 * FF + col]) = make_float2(acc[nt][2] + b0, acc[nt][3] + b1);
        }
    }
}

// ---------------- Kernel B: a_s = h0@att_src, a_d = h0@att_dst -------------
__global__ void __launch_bounds__(256) attvec(const float* __restrict__ att_src,
                                              const float* __restrict__ att_dst) {
    int gw   = (blockIdx.x * blockDim.x + threadIdx.x) >> 5;
    int lane = threadIdx.x & 31;
    if (gw >= NN) return;
    float s = 0.f, d = 0.f;
    for (int c = lane; c < FF; c += 32) {
        float h = g_h0[gw * FF + c];
        s = fmaf(h, att_src[c], s);
        d = fmaf(h, att_dst[c], d);
    }
#pragma unroll
    for (int o = 16; o; o >>= 1) {
        s += __shfl_xor_sync(0xffffffffu, s, o);
        d += __shfl_xor_sync(0xffffffffu, d, o);
    }
    if (lane == 0) { g_as[gw] = s; g_ad[gw] = d; }
}

// ---------------- Kernel C: per-row max + softmax denominator --------------
__global__ void __launch_bounds__(256) softprep() {
    __shared__ float s_as[NN];
    __shared__ float red[8];
    int tid = threadIdx.x, lane = tid & 31, wid = tid >> 5;
    float lm = -1e30f;
    for (int j = tid; j < NN; j += 256) {
        float v = g_as[j];
        s_as[j] = v;
        lm = fmaxf(lm, v);
    }
#pragma unroll
    for (int o = 16; o; o >>= 1) lm = fmaxf(lm, __shfl_xor_sync(0xffffffffu, lm, o));
    if (lane == 0) red[wid] = lm;
    __syncthreads();
    float maxs = red[0];
#pragma unroll
    for (int w = 1; w < 8; w++) maxs = fmaxf(maxs, red[w]);

    int row = blockIdx.x * 8 + wid;
    float ad = g_ad[row];
    float mi = leaky(ad + maxs);
    float sum = 0.f;
    for (int j = lane; j < NN; j += 32)
        sum += __expf(leaky(ad + s_as[j]) - mi);
#pragma unroll
    for (int o = 16; o; o >>= 1) sum += __shfl_xor_sync(0xffffffffu, sum, o);
    if (lane == 0) { g_m[row] = mi; g_den[row] = sum; }
}

// ---------------- Kernel D: partial[ks] = E_chunk @ h0_chunk ---------------
#define DM 32
__global__ void __launch_bounds__(200) attn_gemm() {
    __shared__ __align__(16) float sh_h[DM * FF];
    __shared__ __align__(16) float sh_e[DM * DM];
    const int tid = threadIdx.x;
    const int cg = tid % 25;
    const int ig = tid / 25;
    const int row0 = blockIdx.x * DM;
    const int ks = blockIdx.y;          // j in [ks*128, ks*128+128)

    float acc[4][8];
#pragma unroll
    for (int v = 0; v < 4; v++)
#pragma unroll
        for (int u = 0; u < 8; u++) acc[v][u] = 0.f;

    for (int j0 = ks * 128; j0 < ks * 128 + 128; j0 += DM) {
#pragma unroll
        for (int t = 0; t < 8; t++) {
            int idx = tid + t * 200;
            int j = idx / 50, n4 = idx % 50;
            *reinterpret_cast<float4*>(&sh_h[j * FF + n4 * 4]) =
                *reinterpret_cast<const float4*>(&g_h0[(j0 + j) * FF + n4 * 4]);
        }
        for (int idx = tid; idx < DM * DM; idx += 200) {
            int j = idx >> 5, i = idx & 31;
            float z = leaky(g_ad[row0 + i] + g_as[j0 + j]);
            sh_e[j * DM + i] = __expf(z - g_m[row0 + i]);
        }
        __syncthreads();
#pragma unroll 4
        for (int j = 0; j < DM; j++) {
            float4 ev  = *reinterpret_cast<const float4*>(&sh_e[j * DM + ig * 4]);
            float4 h0v = *reinterpret_cast<const float4*>(&sh_h[j * FF + cg * 8]);
            float4 h1v = *reinterpret_cast<const float4*>(&sh_h[j * FF + cg * 8 + 4]);
            float e[4] = {ev.x, ev.y, ev.z, ev.w};
            float h[8] = {h0v.x, h0v.y, h0v.z, h0v.w, h1v.x, h1v.y, h1v.z, h1v.w};
#pragma unroll
            for (int v = 0; v < 4; v++)
#pragma unroll
                for (int u = 0; u < 8; u++) acc[v][u] = fmaf(e[v], h[u], acc[v][u]);
        }
        __syncthreads();
    }
    const int col = cg * 8;
#pragma unroll
    for (int v = 0; v < 4; v++) {
        int r = row0 + ig * 4 + v;
        *reinterpret_cast<float4*>(&g_part[ks][r * FF + col]) =
            make_float4(acc[v][0], acc[v][1], acc[v][2], acc[v][3]);
        *reinterpret_cast<float4*>(&g_part[ks][r * FF + col + 4]) =
            make_float4(acc[v][4], acc[v][5], acc[v][6], acc[v][7]);
    }
}

// ---------------- Kernel E: out0 = (sum partials)/den + bias ---------------
__global__ void __launch_bounds__(256) finalize(const float* __restrict__ bias,
                                                float* __restrict__ out) {
    int idx = blockIdx.x * 256 + threadIdx.x;
    if (idx >= NN * FF) return;
    int i = idx / FF, c = idx % FF;
    float s = 0.f;
#pragma unroll
    for (int p = 0; p < KS_ATT; p++) s += g_part[p][idx];
    out[idx] = s / g_den[i] + bias[c];
}

// ---------------------------------------------------------------------------
extern "C" void kernel_launch(void* const* d_in, const int* in_sizes, int n_in,
                              void* d_out, int out_size) {
    const float* x       = (const float*)d_in[0];
    const float* W       = (const float*)d_in[1];
    const float* att_src = (const float*)d_in[2];
    const float* att_dst = (const float*)d_in[3];
    const float* bias    = (const float*)d_in[4];
    float* out = (float*)d_out;

    prep_W<<<(KSTEPS * BNP * BK + 255) / 256, 256>>>(W);
    gemm_mma<<<MTOT / BM, 256>>>(x, bias, out);
    attvec<<<NN * 32 / 256, 256>>>(att_src, att_dst);
    softprep<<<NN / 8, 256>>>();
    attn_gemm<<<dim3(NN / DM, KS_ATT), 200>>>();
    finalize<<<(NN * FF + 255) / 256, 256>>>(bias, out);
}

// round 4
// speedup vs baseline: 3.1155x; 1.3080x over previous
#include <cuda_runtime.h>
#include <cuda_bf16.h>
#include <cstdint>

#define NN   1024
#define FF   200
#define MTOT 65536
#define NEG  0.2f

#define BM 64
#define BK 16
#define KSTEPS 13
#define BNP 208
#define ASTR 24            // smem row stride (bf16) for 16-wide k-chunks; conflict-free ldmatrix

// gemm dynamic smem layout (bytes)
#define SM_AH 0
#define SM_AL 3072
#define SM_BH 6144
#define SM_BL 16128
#define GBUF  26112        // per double-buffer
#define GEMM_SMEM (2 * GBUF)

// attention
#define AT_M   32
#define AT_KC  64
#define AT_SPL 4
#define ESTR   72
// attn dynamic smem layout (bytes)
#define SM_HH0 0
#define SM_HL0 25600
#define SM_HH1 51200
#define SM_HL1 76800
#define SM_EH  102400
#define SM_EL  107008
#define ATT_SMEM 111616

// ---------------- scratch ----------------
__device__ float g_as[NN];
__device__ float g_ad[NN];
__device__ __align__(16) __nv_bfloat16 g_h0h[NN * FF];
__device__ __align__(16) __nv_bfloat16 g_h0l[NN * FF];
__device__ float g_part[AT_SPL][NN * FF];
__device__ float g_denp[AT_SPL][NN];
__device__ __align__(16) __nv_bfloat16 g_Wb_h[KSTEPS * BNP * BK];
__device__ __align__(16) __nv_bfloat16 g_Wb_l[KSTEPS * BNP * BK];

__device__ __forceinline__ float leaky(float z) { return z > 0.f ? z : NEG * z; }

__device__ __forceinline__ void cp_async16(uint32_t dst, const void* src) {
    asm volatile("cp.async.cg.shared.global [%0], [%1], 16;" :: "r"(dst), "l"(src));
}
__device__ __forceinline__ void cp_commit() { asm volatile("cp.async.commit_group;"); }

// ---------------- Kernel P: split W into bf16 hi/lo, blocked [ks][n][16] ---
__global__ void __launch_bounds__(256) prep_W(const float* __restrict__ W) {
    int id = blockIdx.x * 256 + threadIdx.x;
    if (id >= KSTEPS * BNP * BK) return;
    int kk = id % BK;
    int n  = (id / BK) % BNP;
    int ks = id / (BK * BNP);
    int k  = ks * BK + kk;
    float v = (k < FF && n < FF) ? W[k * FF + n] : 0.f;
    __nv_bfloat16 hi = __float2bfloat16_rn(v);
    g_Wb_h[id] = hi;
    g_Wb_l[id] = __float2bfloat16_rn(v - __bfloat162float(hi));
}

// ---------------- Kernel A: h = x @ W (bf16 3-pass), fused a_s/a_d ---------
__global__ void __launch_bounds__(256) gemm_mma(const float* __restrict__ x,
                                                const float* __restrict__ att_src,
                                                const float* __restrict__ att_dst,
                                                const float* __restrict__ bias,
                                                float* __restrict__ out) {
    extern __shared__ __align__(16) char smem[];
    const uint32_t smem_u = (uint32_t)__cvta_generic_to_shared(smem);

    const int tid  = threadIdx.x;
    const int lane = tid & 31;
    const int warp = tid >> 5;
    const int warp_m = warp >> 1;
    const int warp_n = warp & 1;
    const int m_base = warp_m * 16;
    const int n_base = warp_n * 104;
    const int row0 = blockIdx.x * BM;

    const int mi   = lane >> 3;
    const int lrow = lane & 7;
    const uint32_t a_off = ((m_base + lrow + (mi & 1) * 8) * ASTR + (mi >> 1) * 8) * 2;
    const uint32_t b_off0 = ((n_base + lrow) * ASTR + ((lane >> 3) & 1) * 8) * 2;

    float acc[13][4];
#pragma unroll
    for (int t = 0; t < 13; t++)
#pragma unroll
        for (int u = 0; u < 4; u++) acc[t][u] = 0.f;

    const int am = tid >> 2;
    const int af = tid & 3;

    // ---- helpers as lambdas ----
    auto issueB = [&](int ks, int p) {
        const char* srcH = (const char*)g_Wb_h + (size_t)ks * (BNP * BK * 2);
        const char* srcL = (const char*)g_Wb_l + (size_t)ks * (BNP * BK * 2);
        uint32_t baseH = smem_u + p * GBUF + SM_BH;
        uint32_t baseL = smem_u + p * GBUF + SM_BL;
#pragma unroll
        for (int idx = tid; idx < BNP * 2; idx += 256) {
            int n = idx >> 1, half = idx & 1;
            uint32_t doff = (n * ASTR + half * 8) * 2;
            cp_async16(baseH + doff, srcH + idx * 16);
            cp_async16(baseL + doff, srcL + idx * 16);
        }
    };
    auto loadA = [&](int ks) -> float4 {
        int col = ks * BK + af * 4;
        return (col < FF) ? *reinterpret_cast<const float4*>(x + (size_t)(row0 + am) * FF + col)
                          : make_float4(0.f, 0.f, 0.f, 0.f);
    };
    auto storeA = [&](float4 v, int p) {
        __nv_bfloat16 h0 = __float2bfloat16_rn(v.x), h1 = __float2bfloat16_rn(v.y);
        __nv_bfloat16 h2 = __float2bfloat16_rn(v.z), h3 = __float2bfloat16_rn(v.w);
        __nv_bfloat16 l0 = __float2bfloat16_rn(v.x - __bfloat162float(h0));
        __nv_bfloat16 l1 = __float2bfloat16_rn(v.y - __bfloat162float(h1));
        __nv_bfloat16 l2 = __float2bfloat16_rn(v.z - __bfloat162float(h2));
        __nv_bfloat16 l3 = __float2bfloat16_rn(v.w - __bfloat162float(h3));
        uint32_t ph0 = ((uint32_t)__bfloat16_as_ushort(h1) << 16) | __bfloat16_as_ushort(h0);
        uint32_t ph1 = ((uint32_t)__bfloat16_as_ushort(h3) << 16) | __bfloat16_as_ushort(h2);
        uint32_t pl0 = ((uint32_t)__bfloat16_as_ushort(l1) << 16) | __bfloat16_as_ushort(l0);
        uint32_t pl1 = ((uint32_t)__bfloat16_as_ushort(l3) << 16) | __bfloat16_as_ushort(l2);
        char* base = smem + p * GBUF;
        int boff = (am * ASTR + af * 4) * 2;
        *reinterpret_cast<uint32_t*>(base + SM_AH + boff)     = ph0;
        *reinterpret_cast<uint32_t*>(base + SM_AH + boff + 4) = ph1;
        *reinterpret_cast<uint32_t*>(base + SM_AL + boff)     = pl0;
        *reinterpret_cast<uint32_t*>(base + SM_AL + boff + 4) = pl1;
    };

    // ---- prologue: fill buffer 0 ----
    issueB(0, 0);
    cp_commit();
    float4 a0 = loadA(0);
    storeA(a0, 0);
    asm volatile("cp.async.wait_group 0;");
    __syncthreads();

    for (int ks = 0; ks < KSTEPS; ks++) {
        const int p = ks & 1;
        const int np = p ^ 1;
        if (ks + 1 < KSTEPS) { issueB(ks + 1, np); cp_commit(); }
        float4 anext = (ks + 1 < KSTEPS) ? loadA(ks + 1) : make_float4(0.f, 0.f, 0.f, 0.f);

        uint32_t ah_base = smem_u + p * GBUF + SM_AH;
        uint32_t al_base = smem_u + p * GBUF + SM_AL;
        uint32_t bh_base = smem_u + p * GBUF + SM_BH;
        uint32_t bl_base = smem_u + p * GBUF + SM_BL;

        uint32_t ah0, ah1, ah2, ah3, al0, al1, al2, al3;
        asm volatile("ldmatrix.sync.aligned.m8n8.x4.shared.b16 {%0,%1,%2,%3}, [%4];"
                     : "=r"(ah0), "=r"(ah1), "=r"(ah2), "=r"(ah3) : "r"(ah_base + a_off));
        asm volatile("ldmatrix.sync.aligned.m8n8.x4.shared.b16 {%0,%1,%2,%3}, [%4];"
                     : "=r"(al0), "=r"(al1), "=r"(al2), "=r"(al3) : "r"(al_base + a_off));
#pragma unroll
        for (int nt = 0; nt < 13; nt++) {
            uint32_t boff = b_off0 + nt * (8 * ASTR * 2);
            uint32_t bh0, bh1, bl0, bl1;
            asm volatile("ldmatrix.sync.aligned.m8n8.x2.shared.b16 {%0,%1}, [%2];"
                         : "=r"(bh0), "=r"(bh1) : "r"(bh_base + boff));
            asm volatile("ldmatrix.sync.aligned.m8n8.x2.shared.b16 {%0,%1}, [%2];"
                         : "=r"(bl0), "=r"(bl1) : "r"(bl_base + boff));
            asm volatile("mma.sync.aligned.m16n8k16.row.col.f32.bf16.bf16.f32 "
                         "{%0,%1,%2,%3}, {%4,%5,%6,%7}, {%8,%9}, {%0,%1,%2,%3};"
                         : "+f"(acc[nt][0]), "+f"(acc[nt][1]), "+f"(acc[nt][2]), "+f"(acc[nt][3])
                         : "r"(ah0), "r"(ah1), "r"(ah2), "r"(ah3), "r"(bh0), "r"(bh1));
            asm volatile("mma.sync.aligned.m16n8k16.row.col.f32.bf16.bf16.f32 "
                         "{%0,%1,%2,%3}, {%4,%5,%6,%7}, {%8,%9}, {%0,%1,%2,%3};"
                         : "+f"(acc[nt][0]), "+f"(acc[nt][1]), "+f"(acc[nt][2]), "+f"(acc[nt][3])
                         : "r"(ah0), "r"(ah1), "r"(ah2), "r"(ah3), "r"(bl0), "r"(bl1));
            asm volatile("mma.sync.aligned.m16n8k16.row.col.f32.bf16.bf16.f32 "
                         "{%0,%1,%2,%3}, {%4,%5,%6,%7}, {%8,%9}, {%0,%1,%2,%3};"
                         : "+f"(acc[nt][0]), "+f"(acc[nt][1]), "+f"(acc[nt][2]), "+f"(acc[nt][3])
                         : "r"(al0), "r"(al1), "r"(al2), "r"(al3), "r"(bh0), "r"(bh1));
        }
        if (ks + 1 < KSTEPS) storeA(anext, np);
        asm volatile("cp.async.wait_group 0;");
        __syncthreads();
    }

    // ---- epilogue ----
    const int g   = lane >> 2;
    const int tig = lane & 3;
    const int r0 = row0 + m_base + g;
    const int r1 = r0 + 8;
    const bool to_h0 = (row0 < NN);

    if (to_h0) {
        float s0 = 0.f, d0 = 0.f, s1 = 0.f, d1 = 0.f;
#pragma unroll
        for (int nt = 0; nt < 13; nt++) {
            int col = n_base + nt * 8 + tig * 2;
            if (col >= FF) continue;
            // bf16 hi/lo pairs of h0
            __nv_bfloat16 h0a = __float2bfloat16_rn(acc[nt][0]);
            __nv_bfloat16 h0b = __float2bfloat16_rn(acc[nt][1]);
            __nv_bfloat16 h1a = __float2bfloat16_rn(acc[nt][2]);
            __nv_bfloat16 h1b = __float2bfloat16_rn(acc[nt][3]);
            __nv_bfloat16 l0a = __float2bfloat16_rn(acc[nt][0] - __bfloat162float(h0a));
            __nv_bfloat16 l0b = __float2bfloat16_rn(acc[nt][1] - __bfloat162float(h0b));
            __nv_bfloat16 l1a = __float2bfloat16_rn(acc[nt][2] - __bfloat162float(h1a));
            __nv_bfloat16 l1b = __float2bfloat16_rn(acc[nt][3] - __bfloat162float(h1b));
            *reinterpret_cast<uint32_t*>(&g_h0h[r0 * FF + col]) =
                ((uint32_t)__bfloat16_as_ushort(h0b) << 16) | __bfloat16_as_ushort(h0a);
            *reinterpret_cast<uint32_t*>(&g_h0h[r1 * FF + col]) =
                ((uint32_t)__bfloat16_as_ushort(h1b) << 16) | __bfloat16_as_ushort(h1a);
            *reinterpret_cast<uint32_t*>(&g_h0l[r0 * FF + col]) =
                ((uint32_t)__bfloat16_as_ushort(l0b) << 16) | __bfloat16_as_ushort(l0a);
            *reinterpret_cast<uint32_t*>(&g_h0l[r1 * FF + col]) =
                ((uint32_t)__bfloat16_as_ushort(l1b) << 16) | __bfloat16_as_ushort(l1a);
            // a_s / a_d partial dots (exact f32 h)
            float sa = att_src[col], sb = att_src[col + 1];
            float da = att_dst[col], db = att_dst[col + 1];
            s0 = fmaf(acc[nt][0], sa, fmaf(acc[nt][1], sb, s0));
            d0 = fmaf(acc[nt][0], da, fmaf(acc[nt][1], db, d0));
            s1 = fmaf(acc[nt][2], sa, fmaf(acc[nt][3], sb, s1));
            d1 = fmaf(acc[nt][2], da, fmaf(acc[nt][3], db, d1));
        }
        // block reduction into g_as/g_ad (smem reuse; all MMA reads done)
        float* red = reinterpret_cast<float*>(smem);   // 128 floats
        if (tid < 128) red[tid] = 0.f;
        __syncthreads();
        atomicAdd(&red[(r0 - row0)],      s0);
        atomicAdd(&red[64 + (r0 - row0)], d0);
        atomicAdd(&red[(r1 - row0)],      s1);
        atomicAdd(&red[64 + (r1 - row0)], d1);
        __syncthreads();
        if (tid < 64) {
            g_as[row0 + tid] = red[tid];
            g_ad[row0 + tid] = red[64 + tid];
        }
    } else {
#pragma unroll
        for (int nt = 0; nt < 13; nt++) {
            int col = n_base + nt * 8 + tig * 2;
            if (col >= FF) continue;
            float b0 = bias[col], b1 = bias[col + 1];
            *reinterpret_cast<float2*>(&out[(size_t)r0 * FF + col]) =
                make_float2(acc[nt][0] + b0, acc[nt][1] + b1);
            *reinterpret_cast<float2*>(&out[(size_t)r1 * FF + col]) =
                make_float2(acc[nt][2] + b0, acc[nt][3] + b1);
        }
    }
}

// ---------------- Kernel B: attention numerator + denominator (bf16 MMA) ---
// E_ij = exp(leaky(ad_i + as_j))  (no max shift: |scores| <~ 4, overflow-safe)
// part[spl] = E_chunk @ h0_chunk ; denp[spl][i] = sum_j E_ij
__global__ void __launch_bounds__(128) attn_mma() {
    extern __shared__ __align__(16) char smem[];
    const uint32_t smem_u = (uint32_t)__cvta_generic_to_shared(smem);

    const int tid  = threadIdx.x;
    const int lane = tid & 31;
    const int warp = tid >> 5;
    const int wm = warp & 1;           // rows wm*16
    const int wn = warp >> 1;          // 0: nt 0..12, 1: nt 13..24
    const int nt_cnt = wn ? 12 : 13;
    const int n_first = wn * 13;
    const int row0 = blockIdx.x * AT_M;
    const int spl  = blockIdx.y;
    const int j0base = spl * (NN / AT_SPL);

    const int mi   = lane >> 3;
    const int lrow = lane & 7;

    float acc[13][4];
#pragma unroll
    for (int t = 0; t < 13; t++)
#pragma unroll
        for (int u = 0; u < 4; u++) acc[t][u] = 0.f;
    float den_acc = 0.f;

    const uint32_t hoff[2][2] = {{SM_HH0, SM_HL0}, {SM_HH1, SM_HL1}};

    auto issueH = [&](int c, int p) {
        int j0 = j0base + c * AT_KC;
        uint32_t dH = smem_u + hoff[p][0];
        uint32_t dL = smem_u + hoff[p][1];
#pragma unroll
        for (int idx = tid; idx < AT_KC * 25; idx += 128) {
            int j = idx / 25, q = idx % 25;
            uint32_t doff = (j * FF + q * 8) * 2;
            const char* sH = (const char*)g_h0h + ((size_t)(j0 + j) * FF + q * 8) * 2;
            const char* sL = (const char*)g_h0l + ((size_t)(j0 + j) * FF + q * 8) * 2;
            cp_async16(dH + doff, sH);
            cp_async16(dL + doff, sL);
        }
    };

    issueH(0, 0);
    cp_commit();

    const int nchunks = (NN / AT_SPL) / AT_KC;   // 4
    for (int c = 0; c < nchunks; c++) {
        const int p = c & 1;
        if (c + 1 < nchunks) { issueH(c + 1, p ^ 1); cp_commit(); }
        if (c + 1 < nchunks) asm volatile("cp.async.wait_group 1;");
        else                 asm volatile("cp.async.wait_group 0;");
        __syncthreads();   // h[p] visible to all; previous E reads done

        // ---- compute E tile (32 i x 64 j) -> smem hi/lo ----
        const int j0 = j0base + c * AT_KC;
        __nv_bfloat16* Eh = reinterpret_cast<__nv_bfloat16*>(smem + SM_EH);
        __nv_bfloat16* El = reinterpret_cast<__nv_bfloat16*>(smem + SM_EL);
#pragma unroll
        for (int t = 0; t < 16; t++) {
            int idx = tid + t * 128;
            int i = idx >> 6, j = idx & 63;
            float e = __expf(leaky(g_ad[row0 + i] + g_as[j0 + j]));
            __nv_bfloat16 eh = __float2bfloat16_rn(e);
            Eh[i * ESTR + j] = eh;
            El[i * ESTR + j] = __float2bfloat16_rn(e - __bfloat162float(eh));
        }
        __syncthreads();

        // ---- denominator row sums ----
        {
            int rr = tid >> 2, q = tid & 3;
            float s = 0.f;
#pragma unroll
            for (int t = 0; t < 8; t++) {
                __nv_bfloat162 vh = *reinterpret_cast<const __nv_bfloat162*>(&Eh[rr * ESTR + q * 16 + 2 * t]);
                __nv_bfloat162 vl = *reinterpret_cast<const __nv_bfloat162*>(&El[rr * ESTR + q * 16 + 2 * t]);
                s += __bfloat162float(vh.x) + __bfloat162float(vl.x)
                   + __bfloat162float(vh.y) + __bfloat162float(vl.y);
            }
            s += __shfl_xor_sync(0xffffffffu, s, 1);
            s += __shfl_xor_sync(0xffffffffu, s, 2);
            den_acc += s;
        }

        // ---- MMAs ----
        const uint32_t eh_base = smem_u + SM_EH;
        const uint32_t el_base = smem_u + SM_EL;
        const uint32_t hh_base = smem_u + hoff[p][0];
        const uint32_t hl_base = smem_u + hoff[p][1];
#pragma unroll
        for (int kf = 0; kf < AT_KC / 16; kf++) {
            uint32_t a_off = ((wm * 16 + lrow + (mi & 1) * 8) * ESTR + kf * 16 + (mi >> 1) * 8) * 2;
            uint32_t eh0, eh1, eh2, eh3, el0, el1, el2, el3;
            asm volatile("ldmatrix.sync.aligned.m8n8.x4.shared.b16 {%0,%1,%2,%3}, [%4];"
                         : "=r"(eh0), "=r"(eh1), "=r"(eh2), "=r"(eh3) : "r"(eh_base + a_off));
            asm volatile("ldmatrix.sync.aligned.m8n8.x4.shared.b16 {%0,%1,%2,%3}, [%4];"
                         : "=r"(el0), "=r"(el1), "=r"(el2), "=r"(el3) : "r"(el_base + a_off));
            uint32_t b_off0 = ((kf * 16 + (lane & 15)) * FF) * 2;
#pragma unroll
            for (int t = 0; t < 13; t++) {
                if (t >= nt_cnt) break;
                int n0 = (n_first + t) * 8;
                uint32_t boff = b_off0 + n0 * 2;
                uint32_t hh0, hh1, hl0, hl1;
                asm volatile("ldmatrix.sync.aligned.m8n8.x2.trans.shared.b16 {%0,%1}, [%2];"
                             : "=r"(hh0), "=r"(hh1) : "r"(hh_base + boff));
                asm volatile("ldmatrix.sync.aligned.m8n8.x2.trans.shared.b16 {%0,%1}, [%2];"
                             : "=r"(hl0), "=r"(hl1) : "r"(hl_base + boff));
                asm volatile("mma.sync.aligned.m16n8k16.row.col.f32.bf16.bf16.f32 "
                             "{%0,%1,%2,%3}, {%4,%5,%6,%7}, {%8,%9}, {%0,%1,%2,%3};"
                             : "+f"(acc[t][0]), "+f"(acc[t][1]), "+f"(acc[t][2]), "+f"(acc[t][3])
                             : "r"(eh0), "r"(eh1), "r"(eh2), "r"(eh3), "r"(hh0), "r"(hh1));
                asm volatile("mma.sync.aligned.m16n8k16.row.col.f32.bf16.bf16.f32 "
                             "{%0,%1,%2,%3}, {%4,%5,%6,%7}, {%8,%9}, {%0,%1,%2,%3};"
                             : "+f"(acc[t][0]), "+f"(acc[t][1]), "+f"(acc[t][2]), "+f"(acc[t][3])
                             : "r"(eh0), "r"(eh1), "r"(eh2), "r"(eh3), "r"(hl0), "r"(hl1));
                asm volatile("mma.sync.aligned.m16n8k16.row.col.f32.bf16.bf16.f32 "
                             "{%0,%1,%2,%3}, {%4,%5,%6,%7}, {%8,%9}, {%0,%1,%2,%3};"
                             : "+f"(acc[t][0]), "+f"(acc[t][1]), "+f"(acc[t][2]), "+f"(acc[t][3])
                             : "r"(el0), "r"(el1), "r"(el2), "r"(el3), "r"(hh0), "r"(hh1));
            }
        }
        __syncthreads();   // E tile consumed; safe to overwrite next chunk
    }

    // ---- epilogue ----
    const int g   = lane >> 2;
    const int tig = lane & 3;
    const int r0 = row0 + wm * 16 + g;
    const int r1 = r0 + 8;
#pragma unroll
    for (int t = 0; t < 13; t++) {
        if (t >= nt_cnt) break;
        int col = (n_first + t) * 8 + tig * 2;
        *reinterpret_cast<float2*>(&g_part[spl][r0 * FF + col]) = make_float2(acc[t][0], acc[t][1]);
        *reinterpret_cast<float2*>(&g_part[spl][r1 * FF + col]) = make_float2(acc[t][2], acc[t][3]);
    }
    if ((tid & 3) == 0) g_denp[spl][row0 + (tid >> 2)] = den_acc;
}

// ---------------- Kernel C: out0 = (sum parts)/(sum dens) + bias -----------
__global__ void __launch_bounds__(256) finalize(const float* __restrict__ bias,
                                                float* __restrict__ out) {
    int idx = blockIdx.x * 256 + threadIdx.x;
    if (idx >= NN * FF) return;
    int i = idx / FF, c = idx % FF;
    float s = 0.f, den = 0.f;
#pragma unroll
    for (int p = 0; p < AT_SPL; p++) { s += g_part[p][idx]; den += g_denp[p][i]; }
    out[idx] = s / den + bias[c];
}

// ---------------------------------------------------------------------------
extern "C" void kernel_launch(void* const* d_in, const int* in_sizes, int n_in,
                              void* d_out, int out_size) {
    const float* x       = (const float*)d_in[0];
    const float* W       = (const float*)d_in[1];
    const float* att_src = (const float*)d_in[2];
    const float* att_dst = (const float*)d_in[3];
    const float* bias    = (const float*)d_in[4];
    float* out = (float*)d_out;

    cudaFuncSetAttribute(gemm_mma, cudaFuncAttributeMaxDynamicSharedMemorySize, GEMM_SMEM);
    cudaFuncSetAttribute(attn_mma, cudaFuncAttributeMaxDynamicSharedMemorySize, ATT_SMEM);

    prep_W<<<(KSTEPS * BNP * BK + 255) / 256, 256>>>(W);
    gemm_mma<<<MTOT / BM, 256, GEMM_SMEM>>>(x, att_src, att_dst, bias, out);
    attn_mma<<<dim3(NN / AT_M, AT_SPL), 128, ATT_SMEM>>>();
    finalize<<<(NN * FF + 255) / 256, 256>>>(bias, out);
}

// round 6
// speedup vs baseline: 3.7502x; 1.2037x over previous
#include <cuda_runtime.h>
#include <cuda_bf16.h>
#include <cuda_fp16.h>
#include <cstdint>

#define NN   1024
#define FF   200
#define MTOT 65536
#define NEG  0.2f

#define BM 64
#define BK 16
#define KSTEPS 13
#define BNP 208
#define ASTR 24            // smem row stride (16-bit elems); 48B rows, conflict-free ldmatrix

// h0-path (3-pass bf16) smem layout per buffer
#define SM_AH 0
#define SM_AL 3072
#define SM_BH 6144
#define SM_BL 16128
#define GBUF  26112
#define GEMM_SMEM (2 * GBUF)     // 52224
// main-path (fp16 single pass) smem layout per buffer
#define F_A 0
#define F_B 3072
#define FBUF 13056

// attention (fp16 single pass)
#define AT_M   32
#define AT_KC  64
#define AT_SPL 4
#define ESTR   72
#define SM_HH0 0
#define SM_HH1 25600
#define SM_E   51200
#define ATT_SMEM 55936

// ---------------- scratch ----------------
__device__ float g_as[NN];
__device__ float g_ad[NN];
__device__ __align__(16) __half g_h0f[NN * FF];
__device__ float g_part[AT_SPL][NN * FF];
__device__ float g_denp[AT_SPL][NN];
// W blocked [ks][n][16]: fp16 for main path, bf16 hi/lo for h0 path
__device__ __align__(16) __half        g_Wf[KSTEPS * BNP * BK];
__device__ __align__(16) __nv_bfloat16 g_Wb_h[KSTEPS * BNP * BK];
__device__ __align__(16) __nv_bfloat16 g_Wb_l[KSTEPS * BNP * BK];

__device__ __forceinline__ float leaky(float z) { return z > 0.f ? z : NEG * z; }

__device__ __forceinline__ void cp_async16(uint32_t dst, const void* src) {
    asm volatile("cp.async.cg.shared.global [%0], [%1], 16;" :: "r"(dst), "l"(src));
}
__device__ __forceinline__ void cp_commit() { asm volatile("cp.async.commit_group;"); }

// ---------------- Kernel P: W -> fp16 + bf16 hi/lo, blocked [ks][n][16] ----
__global__ void __launch_bounds__(256) prep_W(const float* __restrict__ W) {
    int id = blockIdx.x * 256 + threadIdx.x;
    if (id >= KSTEPS * BNP * BK) return;
    int kk = id % BK;
    int n  = (id / BK) % BNP;
    int ks = id / (BK * BNP);
    int k  = ks * BK + kk;
    float v = (k < FF && n < FF) ? W[k * FF + n] : 0.f;
    g_Wf[id] = __float2half_rn(v);
    __nv_bfloat16 hi = __float2bfloat16_rn(v);
    g_Wb_h[id] = hi;
    g_Wb_l[id] = __float2bfloat16_rn(v - __bfloat162float(hi));
}

// ---------------- Kernel A: h = x @ W  (branch: h0 bf16-3pass / main fp16) -
__global__ void __launch_bounds__(256) gemm_mma(const float* __restrict__ x,
                                                const float* __restrict__ att_src,
                                                const float* __restrict__ att_dst,
                                                const float* __restrict__ bias,
                                                float* __restrict__ out) {
    extern __shared__ __align__(16) char smem[];
    const uint32_t smem_u = (uint32_t)__cvta_generic_to_shared(smem);

    const int tid  = threadIdx.x;
    const int lane = tid & 31;
    const int warp = tid >> 5;
    const int warp_m = warp >> 1;
    const int warp_n = warp & 1;
    const int m_base = warp_m * 16;
    const int n_base = warp_n * 104;
    const int row0 = blockIdx.x * BM;

    const int mi   = lane >> 3;
    const int lrow = lane & 7;
    const uint32_t a_off = ((m_base + lrow + (mi & 1) * 8) * ASTR + (mi >> 1) * 8) * 2;
    const uint32_t b_off0 = ((n_base + lrow) * ASTR + ((lane >> 3) & 1) * 8) * 2;

    float acc[13][4];
#pragma unroll
    for (int t = 0; t < 13; t++)
#pragma unroll
        for (int u = 0; u < 4; u++) acc[t][u] = 0.f;

    const int am = tid >> 2;
    const int af = tid & 3;

    auto loadA = [&](int ks) -> float4 {
        int col = ks * BK + af * 4;
        return (col < FF) ? *reinterpret_cast<const float4*>(x + (size_t)(row0 + am) * FF + col)
                          : make_float4(0.f, 0.f, 0.f, 0.f);
    };

    if (row0 >= NN) {
        // =================== MAIN PATH: single-pass fp16 ===================
        auto issueB = [&](int ks, int p) {
            const char* src = (const char*)g_Wf + (size_t)ks * (BNP * BK * 2);
            uint32_t base = smem_u + p * FBUF + F_B;
#pragma unroll
            for (int idx = tid; idx < BNP * 2; idx += 256) {
                int n = idx >> 1, half = idx & 1;
                cp_async16(base + (n * ASTR + half * 8) * 2, src + idx * 16);
            }
        };
        auto storeA = [&](float4 v, int p) {
            __half2 pa = __floats2half2_rn(v.x, v.y);
            __half2 pb = __floats2half2_rn(v.z, v.w);
            char* base = smem + p * FBUF;
            int boff = (am * ASTR + af * 4) * 2;
            *reinterpret_cast<uint32_t*>(base + F_A + boff)     = *reinterpret_cast<uint32_t*>(&pa);
            *reinterpret_cast<uint32_t*>(base + F_A + boff + 4) = *reinterpret_cast<uint32_t*>(&pb);
        };

        issueB(0, 0);
        cp_commit();
        storeA(loadA(0), 0);
        asm volatile("cp.async.wait_group 0;");
        __syncthreads();

        for (int ks = 0; ks < KSTEPS; ks++) {
            const int p = ks & 1;
            const int np = p ^ 1;
            if (ks + 1 < KSTEPS) { issueB(ks + 1, np); cp_commit(); }
            float4 anext = (ks + 1 < KSTEPS) ? loadA(ks + 1) : make_float4(0.f, 0.f, 0.f, 0.f);

            uint32_t aF = smem_u + p * FBUF + F_A;
            uint32_t bF = smem_u + p * FBUF + F_B;
            uint32_t a0, a1, a2, a3;
            asm volatile("ldmatrix.sync.aligned.m8n8.x4.shared.b16 {%0,%1,%2,%3}, [%4];"
                         : "=r"(a0), "=r"(a1), "=r"(a2), "=r"(a3) : "r"(aF + a_off));
#pragma unroll
            for (int nt = 0; nt < 13; nt++) {
                uint32_t b0, b1;
                asm volatile("ldmatrix.sync.aligned.m8n8.x2.shared.b16 {%0,%1}, [%2];"
                             : "=r"(b0), "=r"(b1) : "r"(bF + b_off0 + nt * (8 * ASTR * 2)));
                asm volatile("mma.sync.aligned.m16n8k16.row.col.f32.f16.f16.f32 "
                             "{%0,%1,%2,%3}, {%4,%5,%6,%7}, {%8,%9}, {%0,%1,%2,%3};"
                             : "+f"(acc[nt][0]), "+f"(acc[nt][1]), "+f"(acc[nt][2]), "+f"(acc[nt][3])
                             : "r"(a0), "r"(a1), "r"(a2), "r"(a3), "r"(b0), "r"(b1));
            }
            if (ks + 1 < KSTEPS) storeA(anext, np);
            asm volatile("cp.async.wait_group 0;");
            __syncthreads();
        }

        const int g   = lane >> 2;
        const int tig = lane & 3;
        const int r0 = row0 + m_base + g;
        const int r1 = r0 + 8;
#pragma unroll
        for (int nt = 0; nt < 13; nt++) {
            int col = n_base + nt * 8 + tig * 2;
            if (col >= FF) continue;
            float b0 = bias[col], b1 = bias[col + 1];
            *reinterpret_cast<float2*>(&out[(size_t)r0 * FF + col]) =
                make_float2(acc[nt][0] + b0, acc[nt][1] + b1);
            *reinterpret_cast<float2*>(&out[(size_t)r1 * FF + col]) =
                make_float2(acc[nt][2] + b0, acc[nt][3] + b1);
        }
        return;
    }

    // ===================== H0 PATH: 3-pass bf16 ============================
    auto issueB = [&](int ks, int p) {
        const char* srcH = (const char*)g_Wb_h + (size_t)ks * (BNP * BK * 2);
        const char* srcL = (const char*)g_Wb_l + (size_t)ks * (BNP * BK * 2);
        uint32_t baseH = smem_u + p * GBUF + SM_BH;
        uint32_t baseL = smem_u + p * GBUF + SM_BL;
#pragma unroll
        for (int idx = tid; idx < BNP * 2; idx += 256) {
            int n = idx >> 1, half = idx & 1;
            uint32_t doff = (n * ASTR + half * 8) * 2;
            cp_async16(baseH + doff, srcH + idx * 16);
            cp_async16(baseL + doff, srcL + idx * 16);
        }
    };
    auto storeA = [&](float4 v, int p) {
        __nv_bfloat16 h0 = __float2bfloat16_rn(v.x), h1 = __float2bfloat16_rn(v.y);
        __nv_bfloat16 h2 = __float2bfloat16_rn(v.z), h3 = __float2bfloat16_rn(v.w);
        __nv_bfloat16 l0 = __float2bfloat16_rn(v.x - __bfloat162float(h0));
        __nv_bfloat16 l1 = __float2bfloat16_rn(v.y - __bfloat162float(h1));
        __nv_bfloat16 l2 = __float2bfloat16_rn(v.z - __bfloat162float(h2));
        __nv_bfloat16 l3 = __float2bfloat16_rn(v.w - __bfloat162float(h3));
        uint32_t ph0 = ((uint32_t)__bfloat16_as_ushort(h1) << 16) | __bfloat16_as_ushort(h0);
        uint32_t ph1 = ((uint32_t)__bfloat16_as_ushort(h3) << 16) | __bfloat16_as_ushort(h2);
        uint32_t pl0 = ((uint32_t)__bfloat16_as_ushort(l1) << 16) | __bfloat16_as_ushort(l0);
        uint32_t pl1 = ((uint32_t)__bfloat16_as_ushort(l3) << 16) | __bfloat16_as_ushort(l2);
        char* base = smem + p * GBUF;
        int boff = (am * ASTR + af * 4) * 2;
        *reinterpret_cast<uint32_t*>(base + SM_AH + boff)     = ph0;
        *reinterpret_cast<uint32_t*>(base + SM_AH + boff + 4) = ph1;
        *reinterpret_cast<uint32_t*>(base + SM_AL + boff)     = pl0;
        *reinterpret_cast<uint32_t*>(base + SM_AL + boff + 4) = pl1;
    };

    issueB(0, 0);
    cp_commit();
    storeA(loadA(0), 0);
    asm volatile("cp.async.wait_group 0;");
    __syncthreads();

    for (int ks = 0; ks < KSTEPS; ks++) {
        const int p = ks & 1;
        const int np = p ^ 1;
        if (ks + 1 < KSTEPS) { issueB(ks + 1, np); cp_commit(); }
        float4 anext = (ks + 1 < KSTEPS) ? loadA(ks + 1) : make_float4(0.f, 0.f, 0.f, 0.f);

        uint32_t ah_base = smem_u + p * GBUF + SM_AH;
        uint32_t al_base = smem_u + p * GBUF + SM_AL;
        uint32_t bh_base = smem_u + p * GBUF + SM_BH;
        uint32_t bl_base = smem_u + p * GBUF + SM_BL;

        uint32_t ah0, ah1, ah2, ah3, al0, al1, al2, al3;
        asm volatile("ldmatrix.sync.aligned.m8n8.x4.shared.b16 {%0,%1,%2,%3}, [%4];"
                     : "=r"(ah0), "=r"(ah1), "=r"(ah2), "=r"(ah3) : "r"(ah_base + a_off));
        asm volatile("ldmatrix.sync.aligned.m8n8.x4.shared.b16 {%0,%1,%2,%3}, [%4];"
                     : "=r"(al0), "=r"(al1), "=r"(al2), "=r"(al3) : "r"(al_base + a_off));
#pragma unroll
        for (int nt = 0; nt < 13; nt++) {
            uint32_t boff = b_off0 + nt * (8 * ASTR * 2);
            uint32_t bh0, bh1, bl0, bl1;
            asm volatile("ldmatrix.sync.aligned.m8n8.x2.shared.b16 {%0,%1}, [%2];"
                         : "=r"(bh0), "=r"(bh1) : "r"(bh_base + boff));
            asm volatile("ldmatrix.sync.aligned.m8n8.x2.shared.b16 {%0,%1}, [%2];"
                         : "=r"(bl0), "=r"(bl1) : "r"(bl_base + boff));
            asm volatile("mma.sync.aligned.m16n8k16.row.col.f32.bf16.bf16.f32 "
                         "{%0,%1,%2,%3}, {%4,%5,%6,%7}, {%8,%9}, {%0,%1,%2,%3};"
                         : "+f"(acc[nt][0]), "+f"(acc[nt][1]), "+f"(acc[nt][2]), "+f"(acc[nt][3])
                         : "r"(ah0), "r"(ah1), "r"(ah2), "r"(ah3), "r"(bh0), "r"(bh1));
            asm volatile("mma.sync.aligned.m16n8k16.row.col.f32.bf16.bf16.f32 "
                         "{%0,%1,%2,%3}, {%4,%5,%6,%7}, {%8,%9}, {%0,%1,%2,%3};"
                         : "+f"(acc[nt][0]), "+f"(acc[nt][1]), "+f"(acc[nt][2]), "+f"(acc[nt][3])
                         : "r"(ah0), "r"(ah1), "r"(ah2), "r"(ah3), "r"(bl0), "r"(bl1));
            asm volatile("mma.sync.aligned.m16n8k16.row.col.f32.bf16.bf16.f32 "
                         "{%0,%1,%2,%3}, {%4,%5,%6,%7}, {%8,%9}, {%0,%1,%2,%3};"
                         : "+f"(acc[nt][0]), "+f"(acc[nt][1]), "+f"(acc[nt][2]), "+f"(acc[nt][3])
                         : "r"(al0), "r"(al1), "r"(al2), "r"(al3), "r"(bh0), "r"(bh1));
        }
        if (ks + 1 < KSTEPS) storeA(anext, np);
        asm volatile("cp.async.wait_group 0;");
        __syncthreads();
    }

    // h0 epilogue: fp16 h0 store + fused a_s/a_d dots
    const int g   = lane >> 2;
    const int tig = lane & 3;
    const int r0 = row0 + m_base + g;
    const int r1 = r0 + 8;
    float s0 = 0.f, d0 = 0.f, s1 = 0.f, d1 = 0.f;
#pragma unroll
    for (int nt = 0; nt < 13; nt++) {
        int col = n_base + nt * 8 + tig * 2;
        if (col >= FF) continue;
        __half2 p0 = __floats2half2_rn(acc[nt][0], acc[nt][1]);
        __half2 p1 = __floats2half2_rn(acc[nt][2], acc[nt][3]);
        *reinterpret_cast<uint32_t*>(&g_h0f[r0 * FF + col]) = *reinterpret_cast<uint32_t*>(&p0);
        *reinterpret_cast<uint32_t*>(&g_h0f[r1 * FF + col]) = *reinterpret_cast<uint32_t*>(&p1);
        float sa = att_src[col], sb = att_src[col + 1];
        float da = att_dst[col], db = att_dst[col + 1];
        s0 = fmaf(acc[nt][0], sa, fmaf(acc[nt][1], sb, s0));
        d0 = fmaf(acc[nt][0], da, fmaf(acc[nt][1], db, d0));
        s1 = fmaf(acc[nt][2], sa, fmaf(acc[nt][3], sb, s1));
        d1 = fmaf(acc[nt][2], da, fmaf(acc[nt][3], db, d1));
    }
    float* red = reinterpret_cast<float*>(smem);
    if (tid < 128) red[tid] = 0.f;
    __syncthreads();
    atomicAdd(&red[(r0 - row0)],      s0);
    atomicAdd(&red[64 + (r0 - row0)], d0);
    atomicAdd(&red[(r1 - row0)],      s1);
    atomicAdd(&red[64 + (r1 - row0)], d1);
    __syncthreads();
    if (tid < 64) {
        g_as[row0 + tid] = red[tid];
        g_ad[row0 + tid] = red[64 + tid];
    }
}

// ---------------- Kernel B: attention numerator + denominator (fp16 MMA) ---
// E_ij = exp(leaky(ad_i + as_j))  (no max shift: |scores| <~ 4, safe in fp16/f32)
__global__ void __launch_bounds__(128) attn_mma() {
    extern __shared__ __align__(16) char smem[];
    const uint32_t smem_u = (uint32_t)__cvta_generic_to_shared(smem);

    const int tid  = threadIdx.x;
    const int lane = tid & 31;
    const int warp = tid >> 5;
    const int wm = warp & 1;
    const int wn = warp >> 1;
    const int nt_cnt = wn ? 12 : 13;
    const int n_first = wn * 13;
    const int row0 = blockIdx.x * AT_M;
    const int spl  = blockIdx.y;
    const int j0base = spl * (NN / AT_SPL);

    const int mi   = lane >> 3;
    const int lrow = lane & 7;

    float acc[13][4];
#pragma unroll
    for (int t = 0; t < 13; t++)
#pragma unroll
        for (int u = 0; u < 4; u++) acc[t][u] = 0.f;
    float den_acc = 0.f;

    const uint32_t hoff[2] = {SM_HH0, SM_HH1};

    auto issueH = [&](int c, int p) {
        int j0 = j0base + c * AT_KC;
        uint32_t dH = smem_u + hoff[p];
#pragma unroll
        for (int idx = tid; idx < AT_KC * 25; idx += 128) {
            int j = idx / 25, q = idx % 25;
            cp_async16(dH + (j * FF + q * 8) * 2,
                       (const char*)g_h0f + ((size_t)(j0 + j) * FF + q * 8) * 2);
        }
    };

    issueH(0, 0);
    cp_commit();

    const int nchunks = (NN / AT_SPL) / AT_KC;   // 4
    for (int c = 0; c < nchunks; c++) {
        const int p = c & 1;
        if (c + 1 < nchunks) { issueH(c + 1, p ^ 1); cp_commit(); }
        if (c + 1 < nchunks) asm volatile("cp.async.wait_group 1;");
        else                 asm volatile("cp.async.wait_group 0;");
        __syncthreads();

        const int j0 = j0base + c * AT_KC;
        __half* Eh = reinterpret_cast<__half*>(smem + SM_E);
#pragma unroll
        for (int t = 0; t < 16; t++) {
            int idx = tid + t * 128;
            int i = idx >> 6, j = idx & 63;
            float e = __expf(leaky(g_ad[row0 + i] + g_as[j0 + j]));
            Eh[i * ESTR + j] = __float2half_rn(e);
        }
        __syncthreads();

        {   // denominator row sums (from the same fp16 E the MMA consumes)
            int rr = tid >> 2, q = tid & 3;
            float s = 0.f;
#pragma unroll
            for (int t = 0; t < 8; t++) {
                __half2 vh = *reinterpret_cast<const __half2*>(&Eh[rr * ESTR + q * 16 + 2 * t]);
                s += __half2float(vh.x) + __half2float(vh.y);
            }
            s += __shfl_xor_sync(0xffffffffu, s, 1);
            s += __shfl_xor_sync(0xffffffffu, s, 2);
            den_acc += s;
        }

        const uint32_t e_base = smem_u + SM_E;
        const uint32_t h_base = smem_u + hoff[p];
#pragma unroll
        for (int kf = 0; kf < AT_KC / 16; kf++) {
            uint32_t a_off = ((wm * 16 + lrow + (mi & 1) * 8) * ESTR + kf * 16 + (mi >> 1) * 8) * 2;
            uint32_t e0, e1, e2, e3;
            asm volatile("ldmatrix.sync.aligned.m8n8.x4.shared.b16 {%0,%1,%2,%3}, [%4];"
                         : "=r"(e0), "=r"(e1), "=r"(e2), "=r"(e3) : "r"(e_base + a_off));
            uint32_t b_off0 = ((kf * 16 + (lane & 15)) * FF) * 2;
#pragma unroll
            for (int t = 0; t < 13; t++) {
                if (t >= nt_cnt) break;
                uint32_t boff = b_off0 + (n_first + t) * 16;
                uint32_t h0, h1;
                asm volatile("ldmatrix.sync.aligned.m8n8.x2.trans.shared.b16 {%0,%1}, [%2];"
                             : "=r"(h0), "=r"(h1) : "r"(h_base + boff));
                asm volatile("mma.sync.aligned.m16n8k16.row.col.f32.f16.f16.f32 "
                             "{%0,%1,%2,%3}, {%4,%5,%6,%7}, {%8,%9}, {%0,%1,%2,%3};"
                             : "+f"(acc[t][0]), "+f"(acc[t][1]), "+f"(acc[t][2]), "+f"(acc[t][3])
                             : "r"(e0), "r"(e1), "r"(e2), "r"(e3), "r"(h0), "r"(h1));
            }
        }
        __syncthreads();
    }

    const int g   = lane >> 2;
    const int tig = lane & 3;
    const int r0 = row0 + wm * 16 + g;
    const int r1 = r0 + 8;
#pragma unroll
    for (int t = 0; t < 13; t++) {
        if (t >= nt_cnt) break;
        int col = (n_first + t) * 8 + tig * 2;
        *reinterpret_cast<float2*>(&g_part[spl][r0 * FF + col]) = make_float2(acc[t][0], acc[t][1]);
        *reinterpret_cast<float2*>(&g_part[spl][r1 * FF + col]) = make_float2(acc[t][2], acc[t][3]);
    }
    if ((tid & 3) == 0) g_denp[spl][row0 + (tid >> 2)] = den_acc;
}

// ---------------- Kernel C: out0 = (sum parts)/(sum dens) + bias -----------
__global__ void __launch_bounds__(256) finalize(const float* __restrict__ bias,
                                                float* __restrict__ out) {
    int idx = blockIdx.x * 256 + threadIdx.x;
    if (idx >= NN * FF) return;
    int i = idx / FF, c = idx % FF;
    float s = 0.f, den = 0.f;
#pragma unroll
    for (int p = 0; p < AT_SPL; p++) { s += g_part[p][idx]; den += g_denp[p][i]; }
    out[idx] = s / den + bias[c];
}

// ---------------------------------------------------------------------------
extern "C" void kernel_launch(void* const* d_in, const int* in_sizes, int n_in,
                              void* d_out, int out_size) {
    const float* x       = (const float*)d_in[0];
    const float* W       = (const float*)d_in[1];
    const float* att_src = (const float*)d_in[2];
    const float* att_dst = (const float*)d_in[3];
    const float* bias    = (const float*)d_in[4];
    float* out = (float*)d_out;

    cudaFuncSetAttribute(gemm_mma, cudaFuncAttributeMaxDynamicSharedMemorySize, GEMM_SMEM);
    cudaFuncSetAttribute(attn_mma, cudaFuncAttributeMaxDynamicSharedMemorySize, ATT_SMEM);

    prep_W<<<(KSTEPS * BNP * BK + 255) / 256, 256>>>(W);
    gemm_mma<<<MTOT / BM, 256, GEMM_SMEM>>>(x, att_src, att_dst, bias, out);
    attn_mma<<<dim3(NN / AT_M, AT_SPL), 128, ATT_SMEM>>>();
    finalize<<<(NN * FF + 255) / 256, 256>>>(bias, out);
}

// round 7
// speedup vs baseline: 4.8100x; 1.2826x over previous
#include <cuda_runtime.h>
#include <cuda_fp16.h>
#include <cstdint>

#define NN   1024
#define FF   200
#define MTOT 65536
#define NEG  0.2f

#define BM 64
#define KSTEPS 13
#define BNP 208
#define CHUNK_B 6656                 // 208 n-rows x 32B (16 fp16) per k-chunk
#define WSMEM (KSTEPS * CHUNK_B)     // 86528 bytes, W resident in smem

// attention (fp16 single pass)
#define AT_M   32
#define AT_KC  64
#define AT_SPL 4
#define ESTR   72
#define SM_HH0 0
#define SM_HH1 25600
#define SM_E   51200
#define ATT_SMEM 55936

// ---------------- scratch ----------------
__device__ float g_as[NN];
__device__ float g_ad[NN];
__device__ __align__(16) __half g_h0f[NN * FF];
__device__ float g_part[AT_SPL][NN * FF];
__device__ float g_denp[AT_SPL][NN];
// W fp16 in the EXACT smem image (per-chunk, XOR-swizzled 16B granules)
__device__ __align__(16) __half g_Wf[KSTEPS * BNP * 16];

__device__ __forceinline__ float leaky(float z) { return z > 0.f ? z : NEG * z; }

__device__ __forceinline__ void cp_async16(uint32_t dst, const void* src) {
    asm volatile("cp.async.cg.shared.global [%0], [%1], 16;" :: "r"(dst), "l"(src));
}
__device__ __forceinline__ void cp_commit() { asm volatile("cp.async.commit_group;"); }

// ---------------- Kernel P: W -> fp16 smem-image layout --------------------
// byte(c, n, kk) = c*CHUNK_B + n*32 + ((kk>>3) ^ ((n>>2)&1))*16 + (kk&7)*2
__global__ void __launch_bounds__(256) prep_W(const float* __restrict__ W) {
    int id = blockIdx.x * 256 + threadIdx.x;
    if (id >= KSTEPS * BNP * 16) return;
    int kk = id & 15;
    int n  = (id >> 4) % BNP;
    int c  = id / (16 * BNP);
    int k  = c * 16 + kk;
    float v = (k < FF && n < FF) ? W[k * FF + n] : 0.f;
    uint32_t byte = c * CHUNK_B + n * 32 + (((kk >> 3) ^ ((n >> 2) & 1)) << 4) + (kk & 7) * 2;
    g_Wf[byte >> 1] = __float2half_rn(v);
}

// ---------------- Kernel A: h = x @ W, W-resident, A in registers ----------
__global__ void __launch_bounds__(256) gemm_mma(const float* __restrict__ x,
                                                const float* __restrict__ att_src,
                                                const float* __restrict__ att_dst,
                                                const float* __restrict__ bias,
                                                float* __restrict__ out) {
    extern __shared__ __align__(16) char smem[];
    const uint32_t smem_u = (uint32_t)__cvta_generic_to_shared(smem);

    const int tid  = threadIdx.x;
    const int lane = tid & 31;
    const int warp = tid >> 5;
    const int warp_m = warp >> 1;          // 0..3
    const int warp_n = warp & 1;           // 0..1
    const int m_base = warp_m * 16;
    const int n_base = warp_n * 104;
    const int row0 = blockIdx.x * BM;

    // ---- one-time resident W load ----
    for (int idx = tid; idx < WSMEM / 16; idx += 256)
        cp_async16(smem_u + idx * 16, (const char*)g_Wf + idx * 16);
    cp_commit();
    asm volatile("cp.async.wait_group 0;" ::: "memory");
    __syncthreads();

    // ---- A addressing (register fragments straight from gmem) ----
    const int r   = lane >> 2;
    const int c2  = (lane & 3) * 2;
    const float* xr0 = x + (size_t)(row0 + m_base + r) * FF;
    const float* xr1 = xr0 + 8 * FF;

    // ---- B ldmatrix per-lane address (swizzled, constant across tiles) ----
    const int lrow = lane & 7;
    const int half = (lane >> 3) & 1;
    const uint32_t b_lane = (uint32_t)(n_base + lrow) * 32
                          + ((half ^ ((lrow >> 2) & 1)) << 4);

    float acc[13][4];
#pragma unroll
    for (int t = 0; t < 13; t++)
#pragma unroll
        for (int u = 0; u < 4; u++) acc[t][u] = 0.f;

    float2 f0, f1, f2, f3;
    {
        f0 = *reinterpret_cast<const float2*>(xr0 + c2);
        f1 = *reinterpret_cast<const float2*>(xr1 + c2);
        f2 = *reinterpret_cast<const float2*>(xr0 + c2 + 8);
        f3 = *reinterpret_cast<const float2*>(xr1 + c2 + 8);
    }
#pragma unroll
    for (int ks = 0; ks < KSTEPS; ks++) {
        // prefetch next k-step's A
        float2 n0, n1, n2, n3;
        if (ks + 1 < KSTEPS) {
            int col = (ks + 1) * 16 + c2;
            n0 = *reinterpret_cast<const float2*>(xr0 + col);
            n1 = *reinterpret_cast<const float2*>(xr1 + col);
            if (ks + 1 < KSTEPS - 1) {      // ks+1 == 12 -> cols 200..207 invalid
                n2 = *reinterpret_cast<const float2*>(xr0 + col + 8);
                n3 = *reinterpret_cast<const float2*>(xr1 + col + 8);
            } else {
                n2 = make_float2(0.f, 0.f);
                n3 = n2;
            }
        }
        __half2 ha0 = __floats2half2_rn(f0.x, f0.y);
        __half2 ha1 = __floats2half2_rn(f1.x, f1.y);
        __half2 ha2 = __floats2half2_rn(f2.x, f2.y);
        __half2 ha3 = __floats2half2_rn(f3.x, f3.y);
        uint32_t a0 = *reinterpret_cast<uint32_t*>(&ha0);
        uint32_t a1 = *reinterpret_cast<uint32_t*>(&ha1);
        uint32_t a2 = *reinterpret_cast<uint32_t*>(&ha2);
        uint32_t a3 = *reinterpret_cast<uint32_t*>(&ha3);

        const uint32_t cbase = smem_u + ks * CHUNK_B + b_lane;
#pragma unroll
        for (int nt = 0; nt < 13; nt++) {
            uint32_t b0, b1;
            asm volatile("ldmatrix.sync.aligned.m8n8.x2.shared.b16 {%0,%1}, [%2];"
                         : "=r"(b0), "=r"(b1) : "r"(cbase + nt * 256));
            asm volatile("mma.sync.aligned.m16n8k16.row.col.f32.f16.f16.f32 "
                         "{%0,%1,%2,%3}, {%4,%5,%6,%7}, {%8,%9}, {%0,%1,%2,%3};"
                         : "+f"(acc[nt][0]), "+f"(acc[nt][1]), "+f"(acc[nt][2]), "+f"(acc[nt][3])
                         : "r"(a0), "r"(a1), "r"(a2), "r"(a3), "r"(b0), "r"(b1));
        }
        f0 = n0; f1 = n1; f2 = n2; f3 = n3;
    }

    // ---- epilogue ----
    const int g   = lane >> 2;
    const int tig = lane & 3;
    const int r0 = row0 + m_base + g;
    const int r1 = r0 + 8;

    if (row0 >= NN) {
#pragma unroll
        for (int nt = 0; nt < 13; nt++) {
            int col = n_base + nt * 8 + tig * 2;
            if (col >= FF) continue;
            float b0 = bias[col], b1 = bias[col + 1];
            *reinterpret_cast<float2*>(&out[(size_t)r0 * FF + col]) =
                make_float2(acc[nt][0] + b0, acc[nt][1] + b1);
            *reinterpret_cast<float2*>(&out[(size_t)r1 * FF + col]) =
                make_float2(acc[nt][2] + b0, acc[nt][3] + b1);
        }
        return;
    }

    // h0 CTAs: fp16 h0 store + fused a_s/a_d dots from exact f32 accs
    float s0 = 0.f, d0 = 0.f, s1 = 0.f, d1 = 0.f;
#pragma unroll
    for (int nt = 0; nt < 13; nt++) {
        int col = n_base + nt * 8 + tig * 2;
        if (col >= FF) continue;
        __half2 p0 = __floats2half2_rn(acc[nt][0], acc[nt][1]);
        __half2 p1 = __floats2half2_rn(acc[nt][2], acc[nt][3]);
        *reinterpret_cast<uint32_t*>(&g_h0f[r0 * FF + col]) = *reinterpret_cast<uint32_t*>(&p0);
        *reinterpret_cast<uint32_t*>(&g_h0f[r1 * FF + col]) = *reinterpret_cast<uint32_t*>(&p1);
        float sa = att_src[col], sb = att_src[col + 1];
        float da = att_dst[col], db = att_dst[col + 1];
        s0 = fmaf(acc[nt][0], sa, fmaf(acc[nt][1], sb, s0));
        d0 = fmaf(acc[nt][0], da, fmaf(acc[nt][1], db, d0));
        s1 = fmaf(acc[nt][2], sa, fmaf(acc[nt][3], sb, s1));
        d1 = fmaf(acc[nt][2], da, fmaf(acc[nt][3], db, d1));
    }
    __syncthreads();                       // everyone done reading W -> reuse smem
    float* red = reinterpret_cast<float*>(smem);
    if (tid < 128) red[tid] = 0.f;
    __syncthreads();
    atomicAdd(&red[(r0 - row0)],      s0);
    atomicAdd(&red[64 + (r0 - row0)], d0);
    atomicAdd(&red[(r1 - row0)],      s1);
    atomicAdd(&red[64 + (r1 - row0)], d1);
    __syncthreads();
    if (tid < 64) {
        g_as[row0 + tid] = red[tid];
        g_ad[row0 + tid] = red[64 + tid];
    }
}

// ---------------- Kernel B: attention numerator + denominator (fp16 MMA) ---
__global__ void __launch_bounds__(128) attn_mma() {
    extern __shared__ __align__(16) char smem[];
    const uint32_t smem_u = (uint32_t)__cvta_generic_to_shared(smem);

    const int tid  = threadIdx.x;
    const int lane = tid & 31;
    const int warp = tid >> 5;
    const int wm = warp & 1;
    const int wn = warp >> 1;
    const int nt_cnt = wn ? 12 : 13;
    const int n_first = wn * 13;
    const int row0 = blockIdx.x * AT_M;
    const int spl  = blockIdx.y;
    const int j0base = spl * (NN / AT_SPL);

    const int mi   = lane >> 3;
    const int lrow = lane & 7;

    float acc[13][4];
#pragma unroll
    for (int t = 0; t < 13; t++)
#pragma unroll
        for (int u = 0; u < 4; u++) acc[t][u] = 0.f;
    float den_acc = 0.f;

    const uint32_t hoff[2] = {SM_HH0, SM_HH1};

    auto issueH = [&](int c, int p) {
        int j0 = j0base + c * AT_KC;
        uint32_t dH = smem_u + hoff[p];
#pragma unroll
        for (int idx = tid; idx < AT_KC * 25; idx += 128) {
            int j = idx / 25, q = idx % 25;
            cp_async16(dH + (j * FF + q * 8) * 2,
                       (const char*)g_h0f + ((size_t)(j0 + j) * FF + q * 8) * 2);
        }
    };

    issueH(0, 0);
    cp_commit();

    const int nchunks = (NN / AT_SPL) / AT_KC;   // 4
    for (int c = 0; c < nchunks; c++) {
        const int p = c & 1;
        if (c + 1 < nchunks) { issueH(c + 1, p ^ 1); cp_commit(); }
        if (c + 1 < nchunks) asm volatile("cp.async.wait_group 1;");
        else                 asm volatile("cp.async.wait_group 0;");
        __syncthreads();

        const int j0 = j0base + c * AT_KC;
        __half* Eh = reinterpret_cast<__half*>(smem + SM_E);
#pragma unroll
        for (int t = 0; t < 16; t++) {
            int idx = tid + t * 128;
            int i = idx >> 6, j = idx & 63;
            float e = __expf(leaky(g_ad[row0 + i] + g_as[j0 + j]));
            Eh[i * ESTR + j] = __float2half_rn(e);
        }
        __syncthreads();

        {   // denominator row sums (same fp16 E the MMA consumes)
            int rr = tid >> 2, q = tid & 3;
            float s = 0.f;
#pragma unroll
            for (int t = 0; t < 8; t++) {
                __half2 vh = *reinterpret_cast<const __half2*>(&Eh[rr * ESTR + q * 16 + 2 * t]);
                s += __half2float(vh.x) + __half2float(vh.y);
            }
            s += __shfl_xor_sync(0xffffffffu, s, 1);
            s += __shfl_xor_sync(0xffffffffu, s, 2);
            den_acc += s;
        }

        const uint32_t e_base = smem_u + SM_E;
        const uint32_t h_base = smem_u + hoff[p];
#pragma unroll
        for (int kf = 0; kf < AT_KC / 16; kf++) {
            uint32_t a_off = ((wm * 16 + lrow + (mi & 1) * 8) * ESTR + kf * 16 + (mi >> 1) * 8) * 2;
            uint32_t e0, e1, e2, e3;
            asm volatile("ldmatrix.sync.aligned.m8n8.x4.shared.b16 {%0,%1,%2,%3}, [%4];"
                         : "=r"(e0), "=r"(e1), "=r"(e2), "=r"(e3) : "r"(e_base + a_off));
            uint32_t b_off0 = ((kf * 16 + (lane & 15)) * FF) * 2;
#pragma unroll
            for (int t = 0; t < 13; t++) {
                if (t >= nt_cnt) break;
                uint32_t boff = b_off0 + (n_first + t) * 16;
                uint32_t h0, h1;
                asm volatile("ldmatrix.sync.aligned.m8n8.x2.trans.shared.b16 {%0,%1}, [%2];"
                             : "=r"(h0), "=r"(h1) : "r"(h_base + boff));
                asm volatile("mma.sync.aligned.m16n8k16.row.col.f32.f16.f16.f32 "
                             "{%0,%1,%2,%3}, {%4,%5,%6,%7}, {%8,%9}, {%0,%1,%2,%3};"
                             : "+f"(acc[t][0]), "+f"(acc[t][1]), "+f"(acc[t][2]), "+f"(acc[t][3])
                             : "r"(e0), "r"(e1), "r"(e2), "r"(e3), "r"(h0), "r"(h1));
            }
        }
        __syncthreads();
    }

    const int g   = lane >> 2;
    const int tig = lane & 3;
    const int r0 = row0 + wm * 16 + g;
    const int r1 = r0 + 8;
#pragma unroll
    for (int t = 0; t < 13; t++) {
        if (t >= nt_cnt) break;
        int col = (n_first + t) * 8 + tig * 2;
        *reinterpret_cast<float2*>(&g_part[spl][r0 * FF + col]) = make_float2(acc[t][0], acc[t][1]);
        *reinterpret_cast<float2*>(&g_part[spl][r1 * FF + col]) = make_float2(acc[t][2], acc[t][3]);
    }
    if ((tid & 3) == 0) g_denp[spl][row0 + (tid >> 2)] = den_acc;
}

// ---------------- Kernel C: out0 = (sum parts)/(sum dens) + bias -----------
__global__ void __launch_bounds__(256) finalize(const float* __restrict__ bias,
                                                float* __restrict__ out) {
    int idx = blockIdx.x * 256 + threadIdx.x;
    if (idx >= NN * FF) return;
    int i = idx / FF, c = idx % FF;
    float s = 0.f, den = 0.f;
#pragma unroll
    for (int p = 0; p < AT_SPL; p++) { s += g_part[p][idx]; den += g_denp[p][i]; }
    out[idx] = s / den + bias[c];
}

// ---------------------------------------------------------------------------
extern "C" void kernel_launch(void* const* d_in, const int* in_sizes, int n_in,
                              void* d_out, int out_size) {
    const float* x       = (const float*)d_in[0];
    const float* W       = (const float*)d_in[1];
    const float* att_src = (const float*)d_in[2];
    const float* att_dst = (const float*)d_in[3];
    const float* bias    = (const float*)d_in[4];
    float* out = (float*)d_out;

    cudaFuncSetAttribute(gemm_mma, cudaFuncAttributeMaxDynamicSharedMemorySize, WSMEM);
    cudaFuncSetAttribute(attn_mma, cudaFuncAttributeMaxDynamicSharedMemorySize, ATT_SMEM);

    prep_W<<<(KSTEPS * BNP * 16 + 255) / 256, 256>>>(W);
    gemm_mma<<<MTOT / BM, 256, WSMEM>>>(x, att_src, att_dst, bias, out);
    attn_mma<<<dim3(NN / AT_M, AT_SPL), 128, ATT_SMEM>>>();
    finalize<<<(NN * FF + 255) / 256, 256>>>(bias, out);
}